// round 2
// baseline (speedup 1.0000x reference)
#include <cuda_runtime.h>
#include <math.h>

// Problem constants
#define BB 512
#define TT 1024
#define FF 128
#define UU 50
#define GG 200   // 4*U gates

// Scratch: xproj[b*T + t][200] = x[b,t,:] @ kernel   (bias added in recurrence)
__device__ float g_xproj[(size_t)BB * TT * GG];

// ---------------------------------------------------------------------------
// Kernel 1: projection GEMM  xproj = x @ W
//   M = 524288 rows, K = 128, N = 200.
//   Block: 128 rows x 200 cols, 256 threads.
//   W staged TRANSPOSED in smem ([n][k], pitch 132) so per-column K-chunks are
//   LDS.128 with 4-way broadcast, conflict-free. x rows via LDG.128.
//   Per thread: 2 rows x 50 cols register tile -> 100 accumulators.
// ---------------------------------------------------------------------------
#define WPITCH 132
#define PROJ_ROWS 128

__global__ __launch_bounds__(256, 2)
void proj_kernel(const float* __restrict__ x, const float* __restrict__ W) {
    extern __shared__ float wt[];   // [GG][WPITCH]  (transposed W)

    for (int idx = threadIdx.x; idx < FF * GG; idx += 256) {
        int k = idx / GG;
        int n = idx - k * GG;
        wt[n * WPITCH + k] = W[idx];
    }
    __syncthreads();

    const int tx = threadIdx.x & 3;    // col group: cols [tx*50, tx*50+50)
    const int ty = threadIdx.x >> 2;   // row group: rows ty*2, ty*2+1
    const size_t row0 = (size_t)blockIdx.x * PROJ_ROWS + (size_t)ty * 2;

    const float4* __restrict__ xr0 = (const float4*)(x + row0 * FF);
    const float4* __restrict__ xr1 = (const float4*)(x + (row0 + 1) * FF);
    const float* __restrict__ wb = wt + (tx * 50) * WPITCH;

    float acc0[50], acc1[50];
#pragma unroll
    for (int c = 0; c < 50; ++c) { acc0[c] = 0.f; acc1[c] = 0.f; }

#pragma unroll 1
    for (int k4 = 0; k4 < FF / 4; ++k4) {
        float4 a0 = xr0[k4];
        float4 a1 = xr1[k4];
#pragma unroll
        for (int c = 0; c < 50; ++c) {
            float4 w4 = *(const float4*)(wb + c * WPITCH + k4 * 4);
            acc0[c] = fmaf(a0.x, w4.x, acc0[c]);
            acc0[c] = fmaf(a0.y, w4.y, acc0[c]);
            acc0[c] = fmaf(a0.z, w4.z, acc0[c]);
            acc0[c] = fmaf(a0.w, w4.w, acc0[c]);
            acc1[c] = fmaf(a1.x, w4.x, acc1[c]);
            acc1[c] = fmaf(a1.y, w4.y, acc1[c]);
            acc1[c] = fmaf(a1.z, w4.z, acc1[c]);
            acc1[c] = fmaf(a1.w, w4.w, acc1[c]);
        }
    }

    float* o0 = g_xproj + row0 * GG + tx * 50;
    float* o1 = o0 + GG;
#pragma unroll
    for (int c = 0; c < 25; ++c) {
        *(float2*)(o0 + 2 * c) = make_float2(acc0[2 * c], acc0[2 * c + 1]);
        *(float2*)(o1 + 2 * c) = make_float2(acc1[2 * c], acc1[2 * c + 1]);
    }
}

// ---------------------------------------------------------------------------
// Kernel 2: persistent LSTM recurrence + dense head.
//   One CTA per batch row. 224 threads (7 warps), tid<200 = gate threads.
//   Each gate thread keeps its rec_kernel column (50 floats) + bias in regs.
//   h lives in smem (broadcast reads via LDS.128); c lives in regs of tid<50.
//   2 barriers per timestep. Next-step xproj value prefetched one step ahead.
// ---------------------------------------------------------------------------
__device__ __forceinline__ float sigmoidf_(float v) {
    return 1.f / (1.f + expf(-v));
}

__global__ __launch_bounds__(224)
void lstm_kernel(const float* __restrict__ R, const float* __restrict__ bias,
                 const float* __restrict__ dw, const float* __restrict__ db,
                 float* __restrict__ out) {
    __shared__ __align__(16) float h_s[52];
    __shared__ float z_s[200];

    const int tid = threadIdx.x;
    const int b = blockIdx.x;

    float rw[UU];
    float bv = 0.f;
    if (tid < GG) {
#pragma unroll
        for (int u = 0; u < UU; ++u) rw[u] = R[u * GG + tid];
        bv = bias[tid];
    }
    if (tid < 52) h_s[tid] = 0.f;
    float c = 0.f;
    __syncthreads();

    const float* __restrict__ xp = g_xproj + (size_t)b * TT * GG;

    float xv = (tid < GG) ? xp[tid] : 0.f;   // prefetch t=0

#pragma unroll 1
    for (int t = 0; t < TT; ++t) {
        float xn = 0.f;
        if (tid < GG) {
            int tn = (t + 1 < TT) ? (t + 1) : (TT - 1);
            xn = xp[tn * GG + tid];          // prefetch next step (hidden by dot)

            // z = h_{t-1} . rec_col  (4 independent accumulator chains)
            float acc4[4] = {0.f, 0.f, 0.f, 0.f};
#pragma unroll
            for (int u4 = 0; u4 < 12; ++u4) {
                float4 h4 = *(const float4*)(h_s + 4 * u4);
                float a = acc4[u4 & 3];
                a = fmaf(rw[4 * u4 + 0], h4.x, a);
                a = fmaf(rw[4 * u4 + 1], h4.y, a);
                a = fmaf(rw[4 * u4 + 2], h4.z, a);
                a = fmaf(rw[4 * u4 + 3], h4.w, a);
                acc4[u4 & 3] = a;
            }
            acc4[0] = fmaf(rw[48], h_s[48], acc4[0]);
            acc4[1] = fmaf(rw[49], h_s[49], acc4[1]);
            float acc = (acc4[0] + acc4[1]) + (acc4[2] + acc4[3]) + (bv + xv);

            // per-gate activation, spread over all 200 threads
            float zv;
            if (tid >= 100 && tid < 150) zv = tanhf(acc);     // g
            else                         zv = sigmoidf_(acc); // i, f, o
            z_s[tid] = zv;
        }
        __syncthreads();
        if (tid < UU) {
            float gi = z_s[tid];
            float gf = z_s[tid + 50];
            float gg = z_s[tid + 100];
            float go = z_s[tid + 150];
            c = fmaf(gf, c, gi * gg);
            h_s[tid] = go * tanhf(c);
        }
        __syncthreads();
        xv = xn;
    }

    // dense head: out[b] = h . dense_w + dense_b
    if (tid < UU) z_s[tid] = h_s[tid] * dw[tid];
    __syncthreads();
    if (tid == 0) {
        float s = db[0];
#pragma unroll
        for (int u = 0; u < UU; ++u) s += z_s[u];
        out[b] = s;
    }
}

// ---------------------------------------------------------------------------
extern "C" void kernel_launch(void* const* d_in, const int* in_sizes, int n_in,
                              void* d_out, int out_size) {
    const float* x    = (const float*)d_in[0];  // [512,1024,128]
    const float* W    = (const float*)d_in[1];  // [128,200]
    const float* R    = (const float*)d_in[2];  // [50,200]
    const float* bias = (const float*)d_in[3];  // [200]
    const float* dw   = (const float*)d_in[4];  // [50]
    const float* db   = (const float*)d_in[5];  // [1]
    float* out = (float*)d_out;                 // [512]
    (void)in_sizes; (void)n_in; (void)out_size;

    const int smem = GG * WPITCH * (int)sizeof(float);  // 105600 B
    cudaFuncSetAttribute(proj_kernel,
                         cudaFuncAttributeMaxDynamicSharedMemorySize, smem);

    proj_kernel<<<(BB * TT) / PROJ_ROWS, 256, smem>>>(x, W);
    lstm_kernel<<<BB, 224>>>(R, bias, dw, db, out);
}

// round 4
// speedup vs baseline: 1.2629x; 1.2629x over previous
#include <cuda_runtime.h>
#include <cuda_bf16.h>
#include <math.h>
#include <stdint.h>

// Problem constants
#define BB 512
#define TT 1024
#define FF 128
#define UU 50
#define GG 200            // 4*U gate columns
#define NROWS (BB * TT)   // 524288 GEMM rows
#define MT16 (NROWS / 16) // 32768 m16 tiles
#define NCTA 148
#define NWARPS (NCTA * 8) // 1184 warps

// Scratch: xproj[b*T + t][200] = x[b,t,:] @ kernel (fp32)
__device__ float g_xproj[(size_t)NROWS * GG];

// ---------------------------------------------------------------------------
// helpers
// ---------------------------------------------------------------------------
__device__ __forceinline__ uint32_t smem_u32(const void* p) {
    uint32_t a;
    asm("{ .reg .u64 t; cvta.to.shared.u64 t, %1; cvt.u32.u64 %0, t; }" : "=r"(a) : "l"(p));
    return a;
}

__device__ __forceinline__ uint32_t bf2pack(float a, float b) {
    __nv_bfloat162 t = __floats2bfloat162_rn(a, b);
    return *reinterpret_cast<uint32_t*>(&t);
}

__device__ __forceinline__ void mma16816(float* d, uint32_t a0, uint32_t a1,
                                         uint32_t a2, uint32_t a3,
                                         uint32_t b0, uint32_t b1) {
    asm volatile(
        "mma.sync.aligned.m16n8k16.row.col.f32.bf16.bf16.f32 "
        "{%0,%1,%2,%3}, {%4,%5,%6,%7}, {%8,%9}, {%0,%1,%2,%3};"
        : "+f"(d[0]), "+f"(d[1]), "+f"(d[2]), "+f"(d[3])
        : "r"(a0), "r"(a1), "r"(a2), "r"(a3), "r"(b0), "r"(b1));
}

__device__ __forceinline__ void ldsm_x2(uint32_t& r0, uint32_t& r1, uint32_t addr) {
    asm volatile("ldmatrix.sync.aligned.m8n8.x2.shared.b16 {%0,%1}, [%2];"
                 : "=r"(r0), "=r"(r1) : "r"(addr));
}

// ---------------------------------------------------------------------------
// Kernel 1: projection GEMM xproj = x @ W via HMMA bf16, 3-term hi/lo split.
//   148 CTAs x 256 threads (8 warps). Each warp owns m16 tiles (grid-stride
//   over 32768 tiles), covers all N=200 (25 n8 tiles) and K=128 (8 k16 steps).
//   A fragments are built IN REGISTERS from GMEM float2 loads (no A smem, no
//   barriers in the mainloop). B = W^T staged hi/lo in smem once, padded
//   stride 136 bf16 (272B) -> conflict-free ldmatrix.
// ---------------------------------------------------------------------------
#define KP 136                       // padded B row stride in bf16
#define BROW (KP * 2)                // 272 bytes
#define SMB_HI 0
#define SMB_LO (GG * BROW)           // 54400
#define SMB_TOTAL (2 * GG * BROW)    // 108800 bytes

__global__ __launch_bounds__(256, 1)
void proj_kernel(const float* __restrict__ x, const float* __restrict__ W) {
    extern __shared__ char smem[];
    const uint32_t sb = smem_u32(smem);
    const int tid = threadIdx.x;
    const int wid = tid >> 5;
    const int lane = tid & 31;

    // Stage B = W^T hi/lo.  W is [128 k][200 n] row-major; Bt[n][k].
    for (int idx = tid; idx < GG * FF; idx += 256) {
        int n = idx >> 7;
        int k = idx & 127;
        float v = W[k * GG + n];
        __nv_bfloat16 hi = __float2bfloat16_rn(v);
        float lo = v - __bfloat162float(hi);
        uint32_t off = (uint32_t)(n * BROW + k * 2);
        *reinterpret_cast<__nv_bfloat16*>(smem + SMB_HI + off) = hi;
        *reinterpret_cast<__nv_bfloat16*>(smem + SMB_LO + off) = __float2bfloat16_rn(lo);
    }
    __syncthreads();

    // ldmatrix lane address offset (lanes 16-31 mirror 0-15; addrs unused there)
    const int l8 = lane & 7;
    const int kadd = ((lane & 15) >> 3) * 8;        // matrix1 lanes -> k+8
    const uint32_t lmOff = (uint32_t)(l8 * BROW + kadd * 2);

    const int r = lane >> 2;     // 0..7  (fragment row)
    const int cq = lane & 3;     // 0..3  (fragment col quad)

    for (int mt = blockIdx.x * 8 + wid; mt < MT16; mt += NWARPS) {
        const size_t row0 = (size_t)mt * 16 + r;

        const float* __restrict__ p0 = x + row0 * FF;        // row r
        const float* __restrict__ p1 = x + (row0 + 8) * FF;  // row r+8

        float acc[25][4];
#pragma unroll
        for (int j = 0; j < 25; ++j) {
            acc[j][0] = 0.f; acc[j][1] = 0.f; acc[j][2] = 0.f; acc[j][3] = 0.f;
        }

#pragma unroll
        for (int kk = 0; kk < 8; ++kk) {
            const int k0 = kk * 16;
            // A fragment floats: (r,k0+2c),(r+8,k0+2c),(r,k0+2c+8),(r+8,k0+2c+8)
            float2 f0 = *(const float2*)(p0 + k0 + 2 * cq);
            float2 f1 = *(const float2*)(p1 + k0 + 2 * cq);
            float2 f2 = *(const float2*)(p0 + k0 + 2 * cq + 8);
            float2 f3 = *(const float2*)(p1 + k0 + 2 * cq + 8);

            float h0x = __bfloat162float(__float2bfloat16_rn(f0.x));
            float h0y = __bfloat162float(__float2bfloat16_rn(f0.y));
            float h1x = __bfloat162float(__float2bfloat16_rn(f1.x));
            float h1y = __bfloat162float(__float2bfloat16_rn(f1.y));
            float h2x = __bfloat162float(__float2bfloat16_rn(f2.x));
            float h2y = __bfloat162float(__float2bfloat16_rn(f2.y));
            float h3x = __bfloat162float(__float2bfloat16_rn(f3.x));
            float h3y = __bfloat162float(__float2bfloat16_rn(f3.y));

            uint32_t ah0 = bf2pack(h0x, h0y), ah1 = bf2pack(h1x, h1y);
            uint32_t ah2 = bf2pack(h2x, h2y), ah3 = bf2pack(h3x, h3y);
            uint32_t al0 = bf2pack(f0.x - h0x, f0.y - h0y);
            uint32_t al1 = bf2pack(f1.x - h1x, f1.y - h1y);
            uint32_t al2 = bf2pack(f2.x - h2x, f2.y - h2y);
            uint32_t al3 = bf2pack(f3.x - h3x, f3.y - h3y);

            const uint32_t kOff = (uint32_t)(k0 * 2) + lmOff;
#pragma unroll
            for (int j = 0; j < 25; ++j) {
                uint32_t base = sb + (uint32_t)(j * 8 * BROW) + kOff;
                uint32_t bh0, bh1, bl0, bl1;
                ldsm_x2(bh0, bh1, base + SMB_HI);
                ldsm_x2(bl0, bl1, base + SMB_LO);
                mma16816(acc[j], ah0, ah1, ah2, ah3, bh0, bh1);
                mma16816(acc[j], ah0, ah1, ah2, ah3, bl0, bl1);
                mma16816(acc[j], al0, al1, al2, al3, bh0, bh1);
            }
        }

        // store D: thread holds (row r, cols 2cq,2cq+1) and (row r+8, same)
        float* __restrict__ d0 = g_xproj + row0 * GG + 2 * cq;
        float* __restrict__ d1 = g_xproj + (row0 + 8) * GG + 2 * cq;
#pragma unroll
        for (int j = 0; j < 25; ++j) {
            *(float2*)(d0 + j * 8) = make_float2(acc[j][0], acc[j][1]);
            *(float2*)(d1 + j * 8) = make_float2(acc[j][2], acc[j][3]);
        }
    }
}

// ---------------------------------------------------------------------------
// Kernel 2: persistent LSTM recurrence + dense head.
//   2 batch rows per CTA (256 CTAs x 224 threads). tid<200 computes gates for
//   BOTH rows (shared rec_kernel registers, 2 independent FMA chains);
//   tid<50 updates (c,h) of row0, tid 50..99 row1. HW tanh.approx gates.
// ---------------------------------------------------------------------------
__device__ __forceinline__ float fast_tanh(float v) {
    float y;
    asm("tanh.approx.f32 %0, %1;" : "=f"(y) : "f"(v));
    return y;
}
__device__ __forceinline__ float fast_sig(float v) {
    return fmaf(fast_tanh(0.5f * v), 0.5f, 0.5f);
}

__global__ __launch_bounds__(224)
void lstm_kernel(const float* __restrict__ R, const float* __restrict__ bias,
                 const float* __restrict__ dw, const float* __restrict__ db,
                 float* __restrict__ out) {
    __shared__ __align__(16) float h0_s[52];
    __shared__ __align__(16) float h1_s[52];
    __shared__ float z0_s[200];
    __shared__ float z1_s[200];

    const int tid = threadIdx.x;
    const int b0 = blockIdx.x * 2;
    const int b1 = b0 + 1;

    float rw[UU];
    float bv = 0.f;
    if (tid < GG) {
#pragma unroll
        for (int u = 0; u < UU; ++u) rw[u] = R[u * GG + tid];
        bv = bias[tid];
    }
    if (tid < 52) { h0_s[tid] = 0.f; h1_s[tid] = 0.f; }
    float c = 0.f;     // c of row0 (tid<50) or row1 (tid 50..99)
    __syncthreads();

    const float* __restrict__ xp0 = g_xproj + (size_t)b0 * TT * GG;
    const float* __restrict__ xp1 = g_xproj + (size_t)b1 * TT * GG;

    float xv0 = 0.f, xv1 = 0.f;
    if (tid < GG) { xv0 = xp0[tid]; xv1 = xp1[tid]; }

#pragma unroll 1
    for (int t = 0; t < TT; ++t) {
        float xn0 = 0.f, xn1 = 0.f;
        if (tid < GG) {
            int tn = (t + 1 < TT) ? (t + 1) : (TT - 1);
            xn0 = xp0[(size_t)tn * GG + tid];
            xn1 = xp1[(size_t)tn * GG + tid];

            // dual dot products, 8 independent chains
            float a0[4] = {0.f, 0.f, 0.f, 0.f};
            float a1[4] = {0.f, 0.f, 0.f, 0.f};
#pragma unroll
            for (int u4 = 0; u4 < 12; ++u4) {
                float4 g0 = *(const float4*)(h0_s + 4 * u4);
                float4 g1 = *(const float4*)(h1_s + 4 * u4);
                float w0 = rw[4 * u4 + 0], w1 = rw[4 * u4 + 1];
                float w2 = rw[4 * u4 + 2], w3 = rw[4 * u4 + 3];
                float s0 = a0[u4 & 3], s1 = a1[u4 & 3];
                s0 = fmaf(w0, g0.x, s0); s1 = fmaf(w0, g1.x, s1);
                s0 = fmaf(w1, g0.y, s0); s1 = fmaf(w1, g1.y, s1);
                s0 = fmaf(w2, g0.z, s0); s1 = fmaf(w2, g1.z, s1);
                s0 = fmaf(w3, g0.w, s0); s1 = fmaf(w3, g1.w, s1);
                a0[u4 & 3] = s0; a1[u4 & 3] = s1;
            }
            a0[0] = fmaf(rw[48], h0_s[48], a0[0]);
            a0[1] = fmaf(rw[49], h0_s[49], a0[1]);
            a1[0] = fmaf(rw[48], h1_s[48], a1[0]);
            a1[1] = fmaf(rw[49], h1_s[49], a1[1]);
            float z0 = (a0[0] + a0[1]) + (a0[2] + a0[3]) + (bv + xv0);
            float z1 = (a1[0] + a1[1]) + (a1[2] + a1[3]) + (bv + xv1);

            bool isg = (tid >= 100 && tid < 150);
            z0_s[tid] = isg ? fast_tanh(z0) : fast_sig(z0);
            z1_s[tid] = isg ? fast_tanh(z1) : fast_sig(z1);
        }
        __syncthreads();
        if (tid < UU) {
            float gi = z0_s[tid], gf = z0_s[tid + 50];
            float gg = z0_s[tid + 100], go = z0_s[tid + 150];
            c = fmaf(gf, c, gi * gg);
            h0_s[tid] = go * fast_tanh(c);
        } else if (tid < 2 * UU) {
            int u = tid - UU;
            float gi = z1_s[u], gf = z1_s[u + 50];
            float gg = z1_s[u + 100], go = z1_s[u + 150];
            c = fmaf(gf, c, gi * gg);
            h1_s[u] = go * fast_tanh(c);
        }
        __syncthreads();
        xv0 = xn0; xv1 = xn1;
    }

    // dense head
    if (tid == 0) {
        float s = db[0];
#pragma unroll
        for (int u = 0; u < UU; ++u) s += h0_s[u] * dw[u];
        out[b0] = s;
    } else if (tid == 32) {
        float s = db[0];
#pragma unroll
        for (int u = 0; u < UU; ++u) s += h1_s[u] * dw[u];
        out[b1] = s;
    }
}

// ---------------------------------------------------------------------------
extern "C" void kernel_launch(void* const* d_in, const int* in_sizes, int n_in,
                              void* d_out, int out_size) {
    const float* x    = (const float*)d_in[0];  // [512,1024,128]
    const float* W    = (const float*)d_in[1];  // [128,200]
    const float* R    = (const float*)d_in[2];  // [50,200]
    const float* bias = (const float*)d_in[3];  // [200]
    const float* dw   = (const float*)d_in[4];  // [50]
    const float* db   = (const float*)d_in[5];  // [1]
    float* out = (float*)d_out;                 // [512]
    (void)in_sizes; (void)n_in; (void)out_size;

    cudaFuncSetAttribute(proj_kernel,
                         cudaFuncAttributeMaxDynamicSharedMemorySize, SMB_TOTAL);

    proj_kernel<<<NCTA, 256, SMB_TOTAL>>>(x, W);
    lstm_kernel<<<BB / 2, 224>>>(R, bias, dw, db, out);
}